// round 15
// baseline (speedup 1.0000x reference)
#include <cuda_runtime.h>
#include <cuda_bf16.h>
#include <math.h>

// ---------------- problem constants ----------------
#define TSQ   512
#define BATCH 64
#define INP   256
#define HID   1024
#define OUTD  256
#define DT_A  0.05f

// output buffer layout (floats): [output_tensor | input_proj | tot_rnnhid | tot_output]
static const size_t O_OUTT = 0;                                  // (512,64,256)
static const size_t O_IP   = (size_t)TSQ * BATCH * OUTD;         // (64,512,1024)
static const size_t O_HID  = O_IP  + (size_t)BATCH * TSQ * HID;  // (64,512,1024)
static const size_t O_OUT  = O_HID + (size_t)BATCH * TSQ * HID;  // (64,512,256)

// flag padding: one counter per 128-byte L2 line
#define FPAD 32

// ---------------- device scratch (static: no allocations allowed) ----------------
__device__ __nv_bfloat16 g_thB[(size_t)TSQ * BATCH * HID];  // bf16 tanh(h): [t][b][k] (MMA A layout)
__device__ float         g_thbt[(size_t)BATCH * TSQ * HID]; // fp32 tanh(h): [b][t][k] (output-GEMM layout)
__device__ unsigned      g_tflag[TSQ * 4 * 4 * FPAD];       // th-ready counters (per t, b-tile, k-quarter), 8 arrivals
__device__ float         g_WinT [(size_t)HID * INP];        // tf32(Win^T):  [h][i]
__device__ float         g_WoutT[(size_t)OUTD * HID];       // tf32(Wout^T): [o][h]

// ---------------- sync helpers ----------------
__device__ __forceinline__ unsigned ld_relax(const unsigned* p) {
    unsigned v;
    asm volatile("ld.relaxed.gpu.global.u32 %0, [%1];" : "=r"(v) : "l"(p) : "memory");
    return v;
}
__device__ __forceinline__ unsigned ld_acq(const unsigned* p) {
    unsigned v;
    asm volatile("ld.acquire.gpu.global.u32 %0, [%1];" : "=r"(v) : "l"(p) : "memory");
    return v;
}
__device__ __forceinline__ void red_rel_add(unsigned* p, unsigned v) {
    asm volatile("red.release.gpu.global.add.u32 [%0], %1;" :: "l"(p), "r"(v) : "memory");
}
// relaxed poll with nanosleep backoff, then one acquire load to establish ordering
__device__ __forceinline__ void wait_flag(const unsigned* p, unsigned target) {
    if (ld_relax(p) < target) {
        do { __nanosleep(100); } while (ld_relax(p) < target);
    }
    (void)ld_acq(p);   // flag is monotonic: acquire-read synchronizes with the releases
}

// ---------------- bf16 / tf32 helpers ----------------
__device__ __forceinline__ unsigned pack_bf16x2(float lo, float hi) {
    unsigned r;
    asm("cvt.rn.bf16x2.f32 %0, %1, %2;" : "=r"(r) : "f"(hi), "f"(lo));
    return r;
}
__device__ __forceinline__ void mma_bf16(float d[4], unsigned a0, unsigned a1, unsigned a2, unsigned a3,
                                         unsigned b0, unsigned b1) {
    asm volatile(
        "mma.sync.aligned.m16n8k16.row.col.f32.bf16.bf16.f32 "
        "{%0,%1,%2,%3}, {%4,%5,%6,%7}, {%8,%9}, {%0,%1,%2,%3};"
        : "+f"(d[0]), "+f"(d[1]), "+f"(d[2]), "+f"(d[3])
        : "r"(a0), "r"(a1), "r"(a2), "r"(a3), "r"(b0), "r"(b1));
}
__device__ __forceinline__ unsigned cvt_tf32(float f) {
    unsigned u;
    asm("cvt.rna.tf32.f32 %0, %1;" : "=r"(u) : "f"(f));
    return u;
}
__device__ __forceinline__ void mma_tf32(float d[4], unsigned a0, unsigned a1, unsigned a2, unsigned a3,
                                         unsigned b0, unsigned b1) {
    asm volatile(
        "mma.sync.aligned.m16n8k8.row.col.f32.tf32.tf32.f32 "
        "{%0,%1,%2,%3}, {%4,%5,%6,%7}, {%8,%9}, {%0,%1,%2,%3};"
        : "+f"(d[0]), "+f"(d[1]), "+f"(d[2]), "+f"(d[3])
        : "r"(a0), "r"(a1), "r"(a2), "r"(a3), "r"(b0), "r"(b1));
}

// =====================================================================
// Kernel T: one-shot transpose + tf32 convert of Win and Wout.
// =====================================================================
__global__ __launch_bounds__(256) void transpose_cvt_kernel(
    const float* __restrict__ Win, const float* __restrict__ Wout)
{
    __shared__ float tile[32][33];
    int bid = blockIdx.x;
    const float* src; float* dst; int R, C;
    if (bid < 256) { src = Win;  dst = g_WinT;  R = INP; C = HID; }
    else           { bid -= 256; src = Wout; dst = g_WoutT; R = HID; C = OUTD; }
    const int tilesC = C / 32;
    const int tr = bid / tilesC, tc = bid % tilesC;
    const int tx = threadIdx.x & 31, ty = threadIdx.x >> 5;   // 32 x 8

#pragma unroll
    for (int j = 0; j < 4; j++)
        tile[ty + 8 * j][tx] = src[(size_t)(tr * 32 + ty + 8 * j) * C + tc * 32 + tx];
    __syncthreads();
#pragma unroll
    for (int j = 0; j < 4; j++)
        dst[(size_t)(tc * 32 + ty + 8 * j) * R + tr * 32 + tx] =
            __uint_as_float(cvt_tf32(tile[tx][ty + 8 * j]));
}

// =====================================================================
// Kernel A: input_proj[b][t][h] = sum_i x[t][b][i] * Win[i][h]  (tf32 MMA)
// (unchanged from round 14 — validated)
// =====================================================================
#define TLD 36   // smem k-stride (floats); 36 mod 32 = 4 -> conflict-free frags

__global__ __launch_bounds__(256) void input_proj_kernel(
    const float* __restrict__ x, float* __restrict__ ip)
{
    __shared__ float As[128 * TLD];
    __shared__ float Bs[64 * TLD];
    unsigned* Asu = (unsigned*)As;
    unsigned* Bsu = (unsigned*)Bs;

    const int tid = threadIdx.x;
    const int r0  = blockIdx.y * 128;
    const int c0  = blockIdx.x * 64;
    const int b   = r0 >> 9;
    const int t0  = r0 & 511;

    const int w    = tid >> 5;
    const int lane = tid & 31;
    const int m0 = (w & 3) * 32;
    const int n0 = (w >> 2) * 32;
    const int lr = lane >> 2;
    const int lc = lane & 3;

    float d[2][4][4];
#pragma unroll
    for (int mt = 0; mt < 2; mt++)
#pragma unroll
        for (int nt = 0; nt < 4; nt++)
#pragma unroll
            for (int i = 0; i < 4; i++) d[mt][nt][i] = 0.f;

    for (int k0 = 0; k0 < INP; k0 += 32) {
#pragma unroll
        for (int it = 0; it < 4; it++) {
            const int idx = tid + 256 * it;
            const int row = idx >> 3, k4 = idx & 7;
            const float4 v = __ldg((const float4*)&x[((size_t)(t0 + row) * BATCH + b) * INP + k0 + k4 * 4]);
            uint4 u;
            u.x = cvt_tf32(v.x); u.y = cvt_tf32(v.y); u.z = cvt_tf32(v.z); u.w = cvt_tf32(v.w);
            *(uint4*)&Asu[row * TLD + k4 * 4] = u;
        }
#pragma unroll
        for (int it = 0; it < 2; it++) {
            const int idx = tid + 256 * it;
            const int row = idx >> 3, k4 = idx & 7;
            const float4 v = __ldg((const float4*)&g_WinT[(size_t)(c0 + row) * INP + k0 + k4 * 4]);
            *(float4*)&Bs[row * TLD + k4 * 4] = v;
        }
        __syncthreads();

#pragma unroll
        for (int kk = 0; kk < 4; kk++) {
            const int kb = kk * 8;
            unsigned a[2][4];
#pragma unroll
            for (int mt = 0; mt < 2; mt++) {
                const int mb = m0 + mt * 16;
                a[mt][0] = Asu[(mb + lr) * TLD + kb + lc];
                a[mt][1] = Asu[(mb + lr + 8) * TLD + kb + lc];
                a[mt][2] = Asu[(mb + lr) * TLD + kb + lc + 4];
                a[mt][3] = Asu[(mb + lr + 8) * TLD + kb + lc + 4];
            }
#pragma unroll
            for (int nt = 0; nt < 4; nt++) {
                const unsigned b0 = Bsu[(n0 + nt * 8 + lr) * TLD + kb + lc];
                const unsigned b1 = Bsu[(n0 + nt * 8 + lr) * TLD + kb + lc + 4];
                mma_tf32(d[0][nt], a[0][0], a[0][1], a[0][2], a[0][3], b0, b1);
                mma_tf32(d[1][nt], a[1][0], a[1][1], a[1][2], a[1][3], b0, b1);
            }
        }
        __syncthreads();
    }

    const int er = lane >> 2, ec = 2 * (lane & 3);
#pragma unroll
    for (int mt = 0; mt < 2; mt++)
#pragma unroll
        for (int nt = 0; nt < 4; nt++) {
            const int r = r0 + m0 + mt * 16 + er;
            const int c = c0 + n0 + nt * 8 + ec;
            *(float2*)&ip[(size_t)r * HID + c]       = make_float2(d[mt][nt][0], d[mt][nt][1]);
            *(float2*)&ip[(size_t)(r + 8) * HID + c] = make_float2(d[mt][nt][2], d[mt][nt][3]);
        }
}

// =====================================================================
// Kernel B: persistent single-hop scan, QUARTER-PIPELINED sync.
// 128 CTAs: bt = bid>>5 (16-batch tile), ct = bid&31 (32-col tile).
// Per step: each warp-pair kq waits only for its k-quarter's 8 producers
// (flag (t,bt,q), 8 arrivals), stages its 8 KB A slice, named-bar (64),
// bf16 MMA; all 8 warps publish fragments to Rs; after one CTA bar, ALL
// 256 threads do the reduce + h-update + tanh + stores (2 values each).
// =====================================================================
#define AUW 516   // smem row stride in uints (= 1032 bf16); 516 mod 32 = 4 -> conflict-free

__global__ __launch_bounds__(256) void rnn_scan_kernel(
    const float* __restrict__ ip, const float* __restrict__ Wr,
    const float* __restrict__ bias, float* __restrict__ hid)
{
    extern __shared__ unsigned smemu[];
    unsigned* Asu = smemu;               // [16][516] uints: bf16 th slice (this step's A)
    unsigned* Bsu = smemu + 16 * AUW;    // [32][516] uints: bf16 Wr^T persistent slice
    float4*   RsLo = (float4*)(smemu + 48 * AUW);   // [8 warps][32 lanes] d[0] fragments
    float4*   RsHi = RsLo + 257;                    // same for d[1] (+1 float4 pad: bank shift)

    const int tid = threadIdx.x;
    const int bid = blockIdx.x;     // 0..127
    const int bt  = bid >> 5;       // 0..3   batch tile (16 rows)
    const int ct  = bid & 31;       // 0..31  col tile (32 cols)

    // ---- persistent B operand: Bs[c][k] = bf16(Wr[k][ct*32+c]) ----
    {
        unsigned short* bsh = (unsigned short*)Bsu;
#pragma unroll 4
        for (int ii = 0; ii < 32; ii++) {
            const int idx = tid + 256 * ii;        // 0..8191 float4s of Wr slice
            const int k = idx >> 3, c4 = idx & 7;
            const float4 v = __ldg((const float4*)&Wr[(size_t)k * HID + ct * 32 + c4 * 4]);
            bsh[(c4 * 4 + 0) * (2 * AUW) + k] = __bfloat16_as_ushort(__float2bfloat16(v.x));
            bsh[(c4 * 4 + 1) * (2 * AUW) + k] = __bfloat16_as_ushort(__float2bfloat16(v.y));
            bsh[(c4 * 4 + 2) * (2 * AUW) + k] = __bfloat16_as_ushort(__float2bfloat16(v.z));
            bsh[(c4 * 4 + 3) * (2 * AUW) + k] = __bfloat16_as_ushort(__float2bfloat16(v.w));
        }
    }

    // ---- MMA coords: warp-pair kq = tid>>6 owns k quarter; jg = n-half ----
    const int w    = tid >> 5;
    const int lane = tid & 31;
    const int kq   = tid >> 6;      // 0..3
    const int jg   = (tid >> 5) & 1;
    const int lr   = lane >> 2;
    const int lc   = lane & 3;
    const int pt   = tid & 63;      // thread index within the warp pair

    // ---- update-phase coords: each thread owns (row, cols 2cp, 2cp+1) ----
    const int urow = tid >> 4;      // 0..15
    const int ucp  = tid & 15;
    const int ucol = ct * 32 + 2 * ucp;
    const float2 biav = *(const float2*)&bias[ucol];
    const size_t hb = (size_t)(bt * 16 + urow) * TSQ;   // hid/ip row base
    // fragment reverse-map constants for (urow, ucol-pair)
    const int rl  = (urow & 7) * 4 + (ucp & 3);
    const int jgu = ucp >> 3;
    const int vsel = (ucp >> 2) & 1;
    const int cb  = urow >> 3;

    float h0 = 0.f, h1 = 0.f;

    __syncthreads();

    for (int t = 0; t < TSQ; t++) {
        const size_t i0 = (hb + t) * HID + ucol;
        const float2 ipv = *(const float2*)&ip[i0];   // prefetch (independent of t-1)

        float s0 = 0.f, s1 = 0.f;
        if (t > 0) {
            // ---- per-pair wait: only the 8 producers of k-quarter kq ----
            wait_flag(&g_tflag[(size_t)(((t - 1) * 4 + bt) * 4 + kq) * FPAD], 8u);

            // ---- stage this pair's A quarter: 16 rows x 32 uint4 (8 KB) ----
            const uint4* src = (const uint4*)&g_thB[((size_t)(t - 1) * BATCH + bt * 16) * HID];
#pragma unroll
            for (int i = 0; i < 8; i++) {
                const int idx = pt + 64 * i;         // 0..511
                const int br = idx >> 5, k4 = idx & 31;
                const uint4 v = __ldcg(&src[(size_t)br * 128 + kq * 32 + k4]);
                *(uint4*)&Asu[br * AUW + kq * 128 + k4 * 4] = v;
            }
            asm volatile("bar.sync %0, 64;" :: "r"(kq + 1) : "memory");

            // ---- bf16 MMA (k16): this warp's K quarter, 2 n-tiles ----
            float d0[4] = {0.f, 0.f, 0.f, 0.f};
            float d1[4] = {0.f, 0.f, 0.f, 0.f};
            const int kb0 = kq * 128;
#pragma unroll 4
            for (int kk = 0; kk < 16; kk++) {
                const int kb = kb0 + kk * 8;
                const unsigned a0 = Asu[lr * AUW + kb + lc];
                const unsigned a1 = Asu[(lr + 8) * AUW + kb + lc];
                const unsigned a2 = Asu[lr * AUW + kb + lc + 4];
                const unsigned a3 = Asu[(lr + 8) * AUW + kb + lc + 4];
                const unsigned b00 = Bsu[(jg * 16 + lr) * AUW + kb + lc];
                const unsigned b01 = Bsu[(jg * 16 + lr) * AUW + kb + lc + 4];
                mma_bf16(d0, a0, a1, a2, a3, b00, b01);
                const unsigned b10 = Bsu[(jg * 16 + 8 + lr) * AUW + kb + lc];
                const unsigned b11 = Bsu[(jg * 16 + 8 + lr) * AUW + kb + lc + 4];
                mma_bf16(d1, a0, a1, a2, a3, b10, b11);
            }

            // ---- publish fragments; one CTA bar; all-thread reduce ----
            RsLo[w * 32 + lane] = make_float4(d0[0], d0[1], d0[2], d0[3]);
            RsHi[w * 32 + lane] = make_float4(d1[0], d1[1], d1[2], d1[3]);
            __syncthreads();

#pragma unroll
            for (int q = 0; q < 4; q++) {
                const float4 f = (vsel ? RsHi : RsLo)[(q * 2 + jgu) * 32 + rl];
                s0 += cb ? f.z : f.x;
                s1 += cb ? f.w : f.y;
            }
        }

        // ---- state update: every thread owns 2 h-values ----
        h0 = (1.f - DT_A) * h0 + DT_A * (s0 + ipv.x + biav.x);
        h1 = (1.f - DT_A) * h1 + DT_A * (s1 + ipv.y + biav.y);
        const float th0 = tanhf(h0), th1 = tanhf(h1);
        // critical-path store: bf16x2 tanh, [t][b][k] layout
        *(unsigned*)&g_thB[((size_t)t * BATCH + bt * 16 + urow) * HID + ucol] =
            pack_bf16x2(th0, th1);
        __threadfence();
        __syncthreads();
        if (tid == 0) red_rel_add(&g_tflag[(size_t)((t * 4 + bt) * 4 + (ct >> 3)) * FPAD], 1u);

        // off-critical-path DRAM stores (consumed only by kernel C)
        *(float2*)&hid[i0]    = make_float2(h0, h1);
        *(float2*)&g_thbt[i0] = make_float2(th0, th1);
    }
}

// =====================================================================
// Kernel C: tot_output = tanh(hid) @ Wout  (tf32 MMA, tanh in g_thbt),
// plus transposed copy output_tensor[t][b][o].
// (unchanged from round 14 — validated)
// =====================================================================
__global__ __launch_bounds__(256) void output_kernel(
    float* __restrict__ tot_out, float* __restrict__ outT)
{
    __shared__ float As[128 * TLD];
    __shared__ float Bs[64 * TLD];
    unsigned* Asu = (unsigned*)As;
    unsigned* Bsu = (unsigned*)Bs;

    const int tid = threadIdx.x;
    const int r0  = blockIdx.y * 128;
    const int c0  = blockIdx.x * 64;

    const int w    = tid >> 5;
    const int lane = tid & 31;
    const int m0 = (w & 3) * 32;
    const int n0 = (w >> 2) * 32;
    const int lr = lane >> 2;
    const int lc = lane & 3;

    float d[2][4][4];
#pragma unroll
    for (int mt = 0; mt < 2; mt++)
#pragma unroll
        for (int nt = 0; nt < 4; nt++)
#pragma unroll
            for (int i = 0; i < 4; i++) d[mt][nt][i] = 0.f;

    for (int k0 = 0; k0 < HID; k0 += 32) {
#pragma unroll
        for (int it = 0; it < 4; it++) {
            const int idx = tid + 256 * it;
            const int row = idx >> 3, k4 = idx & 7;
            const float4 v = __ldcg((const float4*)&g_thbt[(size_t)(r0 + row) * HID + k0 + k4 * 4]);
            uint4 u;
            u.x = cvt_tf32(v.x); u.y = cvt_tf32(v.y); u.z = cvt_tf32(v.z); u.w = cvt_tf32(v.w);
            *(uint4*)&Asu[row * TLD + k4 * 4] = u;
        }
#pragma unroll
        for (int it = 0; it < 2; it++) {
            const int idx = tid + 256 * it;
            const int row = idx >> 3, k4 = idx & 7;
            const float4 v = __ldg((const float4*)&g_WoutT[(size_t)(c0 + row) * HID + k0 + k4 * 4]);
            *(float4*)&Bs[row * TLD + k4 * 4] = v;
        }
        __syncthreads();

#pragma unroll
        for (int kk = 0; kk < 4; kk++) {
            const int kb = kk * 8;
            unsigned a[2][4];
#pragma unroll
            for (int mt = 0; mt < 2; mt++) {
                const int mb = m0 + mt * 16;
                a[mt][0] = Asu[(mb + lr) * TLD + kb + lc];
                a[mt][1] = Asu[(mb + lr + 8) * TLD + kb + lc];
                a[mt][2] = Asu[(mb + lr) * TLD + kb + lc + 4];
                a[mt][3] = Asu[(mb + lr + 8) * TLD + kb + lc + 4];
            }
#pragma unroll
            for (int nt = 0; nt < 4; nt++) {
                const unsigned b0 = Bsu[(n0 + nt * 8 + lr) * TLD + kb + lc];
                const unsigned b1 = Bsu[(n0 + nt * 8 + lr) * TLD + kb + lc + 4];
                mma_tf32(d[0][nt], a[0][0], a[0][1], a[0][2], a[0][3], b0, b1);
                mma_tf32(d[1][nt], a[1][0], a[1][1], a[1][2], a[1][3], b0, b1);
            }
        }
        __syncthreads();
    }

    const int er = lane >> 2, ec = 2 * (lane & 3);
#pragma unroll
    for (int mt = 0; mt < 2; mt++)
#pragma unroll
        for (int nt = 0; nt < 4; nt++) {
            const int r = r0 + m0 + mt * 16 + er;
            const int c = c0 + n0 + nt * 8 + ec;
            const int bb = r >> 9, tt = r & 511;
            const float2 v0 = make_float2(d[mt][nt][0], d[mt][nt][1]);
            const float2 v1 = make_float2(d[mt][nt][2], d[mt][nt][3]);
            *(float2*)&tot_out[(size_t)r * OUTD + c]       = v0;
            *(float2*)&tot_out[(size_t)(r + 8) * OUTD + c] = v1;
            *(float2*)&outT[((size_t)tt * BATCH + bb) * OUTD + c]       = v0;
            *(float2*)&outT[((size_t)(tt + 8) * BATCH + bb) * OUTD + c] = v1;
        }
}

// =====================================================================
// launch
// =====================================================================
extern "C" void kernel_launch(void* const* d_in, const int* in_sizes, int n_in,
                              void* d_out, int out_size)
{
    const float* x    = (const float*)d_in[0];
    const float* Win  = (const float*)d_in[1];
    const float* Wr   = (const float*)d_in[2];
    const float* bias = (const float*)d_in[3];
    const float* Wout = (const float*)d_in[4];

    float* out    = (float*)d_out;
    float* o_outT = out + O_OUTT;
    float* o_ip   = out + O_IP;
    float* o_hid  = out + O_HID;
    float* o_out  = out + O_OUT;

    // reset flag counters each launch (graph-capturable, deterministic replays)
    void* p1 = nullptr;
    cudaGetSymbolAddress(&p1, g_tflag);
    cudaMemsetAsync(p1, 0, (size_t)TSQ * 4 * 4 * FPAD * sizeof(unsigned));

    // smem: A/B tiles 48*516 uints + Rs (514 float4) = 99072 + 8224 = 107296 bytes
    const int smemB = (48 * AUW) * 4 + 514 * 16;
    cudaFuncSetAttribute(rnn_scan_kernel, cudaFuncAttributeMaxDynamicSharedMemorySize, smemB);

    // 0) one-shot transpose + tf32 convert of Win / Wout
    transpose_cvt_kernel<<<512, 256>>>(Win, Wout);

    // 1) input projection (tf32 tensor cores)
    input_proj_kernel<<<dim3(HID / 64, (TSQ * BATCH) / 128), 256>>>(x, o_ip);

    // 2) persistent quarter-pipelined recurrent scan: 128 CTAs
    rnn_scan_kernel<<<128, 256, smemB>>>(o_ip, Wr, bias, o_hid);

    // 3) output projection + transpose (tf32 tensor cores)
    output_kernel<<<dim3(OUTD / 64, (TSQ * BATCH) / 128), 256>>>(o_out, o_outT);
}

// round 16
// speedup vs baseline: 1.1803x; 1.1803x over previous
#include <cuda_runtime.h>
#include <cuda_bf16.h>
#include <math.h>

// ---------------- problem constants ----------------
#define TSQ   512
#define BATCH 64
#define INP   256
#define HID   1024
#define OUTD  256
#define DT_A  0.05f

// output buffer layout (floats): [output_tensor | input_proj | tot_rnnhid | tot_output]
static const size_t O_OUTT = 0;                                  // (512,64,256)
static const size_t O_IP   = (size_t)TSQ * BATCH * OUTD;         // (64,512,1024)
static const size_t O_HID  = O_IP  + (size_t)BATCH * TSQ * HID;  // (64,512,1024)
static const size_t O_OUT  = O_HID + (size_t)BATCH * TSQ * HID;  // (64,512,256)

// flag padding: one counter per 128-byte L2 line
#define FPAD 32

// ---------------- device scratch (static: no allocations allowed) ----------------
__device__ __nv_bfloat16 g_thB[(size_t)TSQ * BATCH * HID];  // bf16 tanh(h): [t][b][k] (MMA A layout)
__device__ float         g_thbt[(size_t)BATCH * TSQ * HID]; // tf32-bit tanh(h): [b][t][k] (output-GEMM layout)
__device__ unsigned      g_tflag[TSQ * 8 * FPAD];           // th-ready counters (per t, b-tile), 32 arrivals
__device__ float         g_WinT [(size_t)HID * INP];        // tf32(Win^T):  [h][i]
__device__ float         g_WoutT[(size_t)OUTD * HID];       // tf32(Wout^T): [o][h]

// ---------------- sync helpers ----------------
__device__ __forceinline__ unsigned ld_relax(const unsigned* p) {
    unsigned v;
    asm volatile("ld.relaxed.gpu.global.u32 %0, [%1];" : "=r"(v) : "l"(p) : "memory");
    return v;
}
__device__ __forceinline__ unsigned ld_acq(const unsigned* p) {
    unsigned v;
    asm volatile("ld.acquire.gpu.global.u32 %0, [%1];" : "=r"(v) : "l"(p) : "memory");
    return v;
}
__device__ __forceinline__ void red_rel_add(unsigned* p, unsigned v) {
    asm volatile("red.release.gpu.global.add.u32 [%0], %1;" :: "l"(p), "r"(v) : "memory");
}
// relaxed poll with short nanosleep backoff, then one acquire load for ordering
__device__ __forceinline__ void wait_flag(const unsigned* p, unsigned target) {
    if (ld_relax(p) < target) {
        do { __nanosleep(32); } while (ld_relax(p) < target);
    }
    (void)ld_acq(p);   // flag is monotonic: acquire-read synchronizes with the releases
}

// ---------------- bf16 / tf32 / cp.async helpers ----------------
__device__ __forceinline__ unsigned pack_bf16x2(float lo, float hi) {
    unsigned r;
    asm("cvt.rn.bf16x2.f32 %0, %1, %2;" : "=r"(r) : "f"(hi), "f"(lo));
    return r;
}
__device__ __forceinline__ void mma_bf16(float d[4], unsigned a0, unsigned a1, unsigned a2, unsigned a3,
                                         unsigned b0, unsigned b1) {
    asm volatile(
        "mma.sync.aligned.m16n8k16.row.col.f32.bf16.bf16.f32 "
        "{%0,%1,%2,%3}, {%4,%5,%6,%7}, {%8,%9}, {%0,%1,%2,%3};"
        : "+f"(d[0]), "+f"(d[1]), "+f"(d[2]), "+f"(d[3])
        : "r"(a0), "r"(a1), "r"(a2), "r"(a3), "r"(b0), "r"(b1));
}
__device__ __forceinline__ unsigned cvt_tf32(float f) {
    unsigned u;
    asm("cvt.rna.tf32.f32 %0, %1;" : "=r"(u) : "f"(f));
    return u;
}
__device__ __forceinline__ void mma_tf32(float d[4], unsigned a0, unsigned a1, unsigned a2, unsigned a3,
                                         unsigned b0, unsigned b1) {
    asm volatile(
        "mma.sync.aligned.m16n8k8.row.col.f32.tf32.tf32.f32 "
        "{%0,%1,%2,%3}, {%4,%5,%6,%7}, {%8,%9}, {%0,%1,%2,%3};"
        : "+f"(d[0]), "+f"(d[1]), "+f"(d[2]), "+f"(d[3])
        : "r"(a0), "r"(a1), "r"(a2), "r"(a3), "r"(b0), "r"(b1));
}
__device__ __forceinline__ unsigned smem_u32(const void* p) {
    unsigned a;
    asm("{ .reg .u64 t; cvta.to.shared.u64 t, %1; cvt.u32.u64 %0, t; }" : "=r"(a) : "l"(p));
    return a;
}
__device__ __forceinline__ void cp_async16(unsigned saddr, const void* gptr) {
    asm volatile("cp.async.cg.shared.global [%0], [%1], 16;" :: "r"(saddr), "l"(gptr));
}
__device__ __forceinline__ void cp_commit() {
    asm volatile("cp.async.commit_group;");
}
template <int N>
__device__ __forceinline__ void cp_wait() {
    asm volatile("cp.async.wait_group %0;" :: "n"(N));
}

// =====================================================================
// Kernel T: one-shot transpose + tf32 convert of Win and Wout.
// =====================================================================
__global__ __launch_bounds__(256) void transpose_cvt_kernel(
    const float* __restrict__ Win, const float* __restrict__ Wout)
{
    __shared__ float tile[32][33];
    int bid = blockIdx.x;
    const float* src; float* dst; int R, C;
    if (bid < 256) { src = Win;  dst = g_WinT;  R = INP; C = HID; }
    else           { bid -= 256; src = Wout; dst = g_WoutT; R = HID; C = OUTD; }
    const int tilesC = C / 32;
    const int tr = bid / tilesC, tc = bid % tilesC;
    const int tx = threadIdx.x & 31, ty = threadIdx.x >> 5;   // 32 x 8

#pragma unroll
    for (int j = 0; j < 4; j++)
        tile[ty + 8 * j][tx] = src[(size_t)(tr * 32 + ty + 8 * j) * C + tc * 32 + tx];
    __syncthreads();
#pragma unroll
    for (int j = 0; j < 4; j++)
        dst[(size_t)(tc * 32 + ty + 8 * j) * R + tr * 32 + tx] =
            __uint_as_float(cvt_tf32(tile[tx][ty + 8 * j]));
}

// =====================================================================
// Kernel A: input_proj[b][t][h] = sum_i x[t][b][i] * Win[i][h]  (tf32 MMA)
// (round-14 version — validated)
// =====================================================================
#define TLD 36   // smem k-stride (floats); 36 mod 32 = 4 -> conflict-free frags

__global__ __launch_bounds__(256) void input_proj_kernel(
    const float* __restrict__ x, float* __restrict__ ip)
{
    __shared__ float As[128 * TLD];
    __shared__ float Bs[64 * TLD];
    unsigned* Asu = (unsigned*)As;
    unsigned* Bsu = (unsigned*)Bs;

    const int tid = threadIdx.x;
    const int r0  = blockIdx.y * 128;
    const int c0  = blockIdx.x * 64;
    const int b   = r0 >> 9;
    const int t0  = r0 & 511;

    const int w    = tid >> 5;
    const int lane = tid & 31;
    const int m0 = (w & 3) * 32;
    const int n0 = (w >> 2) * 32;
    const int lr = lane >> 2;
    const int lc = lane & 3;

    float d[2][4][4];
#pragma unroll
    for (int mt = 0; mt < 2; mt++)
#pragma unroll
        for (int nt = 0; nt < 4; nt++)
#pragma unroll
            for (int i = 0; i < 4; i++) d[mt][nt][i] = 0.f;

    for (int k0 = 0; k0 < INP; k0 += 32) {
#pragma unroll
        for (int it = 0; it < 4; it++) {
            const int idx = tid + 256 * it;
            const int row = idx >> 3, k4 = idx & 7;
            const float4 v = __ldg((const float4*)&x[((size_t)(t0 + row) * BATCH + b) * INP + k0 + k4 * 4]);
            uint4 u;
            u.x = cvt_tf32(v.x); u.y = cvt_tf32(v.y); u.z = cvt_tf32(v.z); u.w = cvt_tf32(v.w);
            *(uint4*)&Asu[row * TLD + k4 * 4] = u;
        }
#pragma unroll
        for (int it = 0; it < 2; it++) {
            const int idx = tid + 256 * it;
            const int row = idx >> 3, k4 = idx & 7;
            const float4 v = __ldg((const float4*)&g_WinT[(size_t)(c0 + row) * INP + k0 + k4 * 4]);
            *(float4*)&Bs[row * TLD + k4 * 4] = v;
        }
        __syncthreads();

#pragma unroll
        for (int kk = 0; kk < 4; kk++) {
            const int kb = kk * 8;
            unsigned a[2][4];
#pragma unroll
            for (int mt = 0; mt < 2; mt++) {
                const int mb = m0 + mt * 16;
                a[mt][0] = Asu[(mb + lr) * TLD + kb + lc];
                a[mt][1] = Asu[(mb + lr + 8) * TLD + kb + lc];
                a[mt][2] = Asu[(mb + lr) * TLD + kb + lc + 4];
                a[mt][3] = Asu[(mb + lr + 8) * TLD + kb + lc + 4];
            }
#pragma unroll
            for (int nt = 0; nt < 4; nt++) {
                const unsigned b0 = Bsu[(n0 + nt * 8 + lr) * TLD + kb + lc];
                const unsigned b1 = Bsu[(n0 + nt * 8 + lr) * TLD + kb + lc + 4];
                mma_tf32(d[0][nt], a[0][0], a[0][1], a[0][2], a[0][3], b0, b1);
                mma_tf32(d[1][nt], a[1][0], a[1][1], a[1][2], a[1][3], b0, b1);
            }
        }
        __syncthreads();
    }

    const int er = lane >> 2, ec = 2 * (lane & 3);
#pragma unroll
    for (int mt = 0; mt < 2; mt++)
#pragma unroll
        for (int nt = 0; nt < 4; nt++) {
            const int r = r0 + m0 + mt * 16 + er;
            const int c = c0 + n0 + nt * 8 + ec;
            *(float2*)&ip[(size_t)r * HID + c]       = make_float2(d[mt][nt][0], d[mt][nt][1]);
            *(float2*)&ip[(size_t)(r + 8) * HID + c] = make_float2(d[mt][nt][2], d[mt][nt][3]);
        }
}

// =====================================================================
// Kernel B: persistent SINGLE-HOP recurrent scan with bf16 mma.sync (k16).
// (round-14 version — validated at 1909 us; deltas: nanosleep 32,
//  g_thbt stored as tf32 bits for kernel C's cp.async path)
// =====================================================================
#define AUW 516   // smem row stride in uints (= 1032 bf16); 516 mod 32 = 4 -> conflict-free

__global__ __launch_bounds__(256) void rnn_scan_kernel(
    const float* __restrict__ ip, const float* __restrict__ Wr,
    const float* __restrict__ bias, float* __restrict__ hid)
{
    extern __shared__ unsigned smemu[];
    unsigned* Asu = smemu;               // [16][516] uints: bf16 th slice (this step's A)
    unsigned* Bsu = smemu + 16 * AUW;    // [32][516] uints: bf16 Wr^T persistent slice
    float*    Rs  = (float*)(smemu + 48 * AUW);   // [1536] cross-warp K-reduce buffer

    const int tid = threadIdx.x;
    const int bid = blockIdx.x;     // 0..127
    const int bt  = bid >> 5;       // 0..3   batch tile (16 rows)
    const int ct  = bid & 31;       // 0..31  col tile (32 cols)

    // ---- persistent B operand: Bs[c][k] = bf16(Wr[k][ct*32+c]) ----
    {
        unsigned short* bsh = (unsigned short*)Bsu;
#pragma unroll 4
        for (int ii = 0; ii < 32; ii++) {
            const int idx = tid + 256 * ii;        // 0..8191 float4s of Wr slice
            const int k = idx >> 3, c4 = idx & 7;
            const float4 v = __ldg((const float4*)&Wr[(size_t)k * HID + ct * 32 + c4 * 4]);
            bsh[(c4 * 4 + 0) * (2 * AUW) + k] = __bfloat16_as_ushort(__float2bfloat16(v.x));
            bsh[(c4 * 4 + 1) * (2 * AUW) + k] = __bfloat16_as_ushort(__float2bfloat16(v.y));
            bsh[(c4 * 4 + 2) * (2 * AUW) + k] = __bfloat16_as_ushort(__float2bfloat16(v.z));
            bsh[(c4 * 4 + 3) * (2 * AUW) + k] = __bfloat16_as_ushort(__float2bfloat16(v.w));
        }
    }

    const int w    = tid >> 5;
    const int lane = tid & 31;
    const int kq   = w >> 1;        // 0..3
    const int jg   = w & 1;         // 0..1
    const int lr   = lane >> 2;     // 0..7
    const int lc   = lane & 3;      // 0..3

    const int r0g = bt * 16 + lr;
    const int r1g = r0g + 8;

    float hreg[2][4];
#pragma unroll
    for (int j2 = 0; j2 < 2; j2++)
#pragma unroll
        for (int i = 0; i < 4; i++) hreg[j2][i] = 0.f;

    float2 bia2[2];
    if (w < 2) {
#pragma unroll
        for (int j2 = 0; j2 < 2; j2++)
            bia2[j2] = *(const float2*)&bias[ct * 32 + jg * 16 + j2 * 8 + 2 * lc];
    }

    __syncthreads();

    for (int t = 0; t < TSQ; t++) {
        float2 ipv[2][2];
        size_t ib[2][2];
        if (w < 2) {
#pragma unroll
            for (int j2 = 0; j2 < 2; j2++) {
                const int cj = ct * 32 + jg * 16 + j2 * 8 + 2 * lc;
                ib[j2][0] = ((size_t)r0g * TSQ + t) * HID + cj;
                ib[j2][1] = ((size_t)r1g * TSQ + t) * HID + cj;
                ipv[j2][0] = *(const float2*)&ip[ib[j2][0]];
                ipv[j2][1] = *(const float2*)&ip[ib[j2][1]];
            }
        }

        float d[2][4];
#pragma unroll
        for (int j2 = 0; j2 < 2; j2++)
#pragma unroll
            for (int i = 0; i < 4; i++) d[j2][i] = 0.f;

        if (t > 0) {
            wait_flag(&g_tflag[(size_t)((t - 1) * 4 + bt) * FPAD], 32u);

            const uint4* src = (const uint4*)&g_thB[((size_t)(t - 1) * BATCH + bt * 16) * HID];
#pragma unroll
            for (int i2 = 0; i2 < 8; i2++) {
                const int idx = tid + 256 * i2;
                const int br = idx >> 7, k4 = idx & 127;
                const uint4 v = __ldcg(&src[(size_t)br * 128 + k4]);
                *(uint4*)&Asu[br * AUW + k4 * 4] = v;
            }
            __syncthreads();

            const int kb0 = kq * 128;
#pragma unroll 4
            for (int kk = 0; kk < 16; kk++) {
                const int kb = kb0 + kk * 8;
                const unsigned a0 = Asu[lr * AUW + kb + lc];
                const unsigned a1 = Asu[(lr + 8) * AUW + kb + lc];
                const unsigned a2 = Asu[lr * AUW + kb + lc + 4];
                const unsigned a3 = Asu[(lr + 8) * AUW + kb + lc + 4];
                const unsigned b00 = Bsu[(jg * 16 + lr) * AUW + kb + lc];
                const unsigned b01 = Bsu[(jg * 16 + lr) * AUW + kb + lc + 4];
                mma_bf16(d[0], a0, a1, a2, a3, b00, b01);
                const unsigned b10 = Bsu[(jg * 16 + 8 + lr) * AUW + kb + lc];
                const unsigned b11 = Bsu[(jg * 16 + 8 + lr) * AUW + kb + lc + 4];
                mma_bf16(d[1], a0, a1, a2, a3, b10, b11);
            }

            if (kq > 0) {
                float* rb = &Rs[(((kq - 1) * 2 + jg) * 32 + lane) * 8];
                *(float4*)&rb[0] = make_float4(d[0][0], d[0][1], d[0][2], d[0][3]);
                *(float4*)&rb[4] = make_float4(d[1][0], d[1][1], d[1][2], d[1][3]);
            }
            __syncthreads();
            if (w < 2) {
#pragma unroll
                for (int q = 0; q < 3; q++) {
                    const float* rb = &Rs[((q * 2 + jg) * 32 + lane) * 8];
                    const float4 p0 = *(const float4*)&rb[0];
                    const float4 p1 = *(const float4*)&rb[4];
                    d[0][0] += p0.x; d[0][1] += p0.y; d[0][2] += p0.z; d[0][3] += p0.w;
                    d[1][0] += p1.x; d[1][1] += p1.y; d[1][2] += p1.z; d[1][3] += p1.w;
                }
            }
        }

        float thv[2][4];
        if (w < 2) {
#pragma unroll
            for (int j2 = 0; j2 < 2; j2++) {
                hreg[j2][0] = (1.f - DT_A) * hreg[j2][0] + DT_A * (d[j2][0] + ipv[j2][0].x + bia2[j2].x);
                hreg[j2][1] = (1.f - DT_A) * hreg[j2][1] + DT_A * (d[j2][1] + ipv[j2][0].y + bia2[j2].y);
                hreg[j2][2] = (1.f - DT_A) * hreg[j2][2] + DT_A * (d[j2][2] + ipv[j2][1].x + bia2[j2].x);
                hreg[j2][3] = (1.f - DT_A) * hreg[j2][3] + DT_A * (d[j2][3] + ipv[j2][1].y + bia2[j2].y);
                thv[j2][0] = tanhf(hreg[j2][0]);
                thv[j2][1] = tanhf(hreg[j2][1]);
                thv[j2][2] = tanhf(hreg[j2][2]);
                thv[j2][3] = tanhf(hreg[j2][3]);
                const int cj = ct * 32 + jg * 16 + j2 * 8 + 2 * lc;
                *(unsigned*)&g_thB[((size_t)t * BATCH + r0g) * HID + cj] =
                    pack_bf16x2(thv[j2][0], thv[j2][1]);
                *(unsigned*)&g_thB[((size_t)t * BATCH + r1g) * HID + cj] =
                    pack_bf16x2(thv[j2][2], thv[j2][3]);
            }
            __threadfence();
        }
        __syncthreads();
        if (tid == 0) red_rel_add(&g_tflag[(size_t)(t * 4 + bt) * FPAD], 1u);

        // off-critical-path DRAM stores (consumed only by kernel C / checker)
        if (w < 2) {
#pragma unroll
            for (int j2 = 0; j2 < 2; j2++) {
                *(float2*)&hid[ib[j2][0]] = make_float2(hreg[j2][0], hreg[j2][1]);
                *(float2*)&hid[ib[j2][1]] = make_float2(hreg[j2][2], hreg[j2][3]);
                // tf32-rounded tanh for kernel C's cp.async path (same numerics as
                // the load-time cvt it replaces)
                *(float2*)&g_thbt[ib[j2][0]] =
                    make_float2(__uint_as_float(cvt_tf32(thv[j2][0])), __uint_as_float(cvt_tf32(thv[j2][1])));
                *(float2*)&g_thbt[ib[j2][1]] =
                    make_float2(__uint_as_float(cvt_tf32(thv[j2][2])), __uint_as_float(cvt_tf32(thv[j2][3])));
            }
        }
    }
}

// =====================================================================
// Kernel C: tot_output = tanh(hid) @ Wout  (tf32 MMA, pre-rounded tanh
// in g_thbt), plus transposed copy output_tensor[t][b][o].
// cp.async double-buffered staging: next k-tile's global->smem copies
// overlap the current tile's MMA.
// =====================================================================
#define CTA_F (128 * TLD)   // A tile floats per buffer
#define CTB_F (64 * TLD)    // B tile floats per buffer

__global__ __launch_bounds__(256) void output_kernel(
    float* __restrict__ tot_out, float* __restrict__ outT)
{
    extern __shared__ float csmem[];
    const unsigned sbase = smem_u32(csmem);

    const int tid = threadIdx.x;
    const int r0  = blockIdx.y * 128;
    const int c0  = blockIdx.x * 64;

    const int w    = tid >> 5;
    const int lane = tid & 31;
    const int m0 = (w & 3) * 32;
    const int n0 = (w >> 2) * 32;
    const int lr = lane >> 2;
    const int lc = lane & 3;

    // per-thread copy slots
    const int arow0 = tid >> 3, ak4 = tid & 7;       // A: 4 chunks (rows arow0 + 32*i)
    const int brow0 = tid >> 3;                       // B: 2 chunks (rows brow0, +32) — same k4

    float d[2][4][4];
#pragma unroll
    for (int mt = 0; mt < 2; mt++)
#pragma unroll
        for (int nt = 0; nt < 4; nt++)
#pragma unroll
            for (int i = 0; i < 4; i++) d[mt][nt][i] = 0.f;

    // tile issue: copy A(128x32) + B(64x32) for k-chunk `it` into buffer `bsel`
    auto issue_tile = [&](int it, int bsel) {
        const int k0 = it * 32;
        const unsigned aoff = sbase + (unsigned)(bsel * CTA_F) * 4u;
        const unsigned boff = sbase + (unsigned)(2 * CTA_F + bsel * CTB_F) * 4u;
#pragma unroll
        for (int i = 0; i < 4; i++) {
            const int row = arow0 + 32 * i;
            cp_async16(aoff + (unsigned)(row * TLD + ak4 * 4) * 4u,
                       &g_thbt[(size_t)(r0 + row) * HID + k0 + ak4 * 4]);
        }
#pragma unroll
        for (int i = 0; i < 2; i++) {
            const int row = brow0 + 32 * i;
            cp_async16(boff + (unsigned)(row * TLD + ak4 * 4) * 4u,
                       &g_WoutT[(size_t)(c0 + row) * HID + k0 + ak4 * 4]);
        }
        cp_commit();
    };

    issue_tile(0, 0);

    for (int it = 0; it < 32; it++) {
        const int bsel = it & 1;
        if (it + 1 < 32) {
            issue_tile(it + 1, bsel ^ 1);
            cp_wait<1>();
        } else {
            cp_wait<0>();
        }
        __syncthreads();

        const unsigned* Asu = (const unsigned*)(csmem + bsel * CTA_F);
        const unsigned* Bsu = (const unsigned*)(csmem + 2 * CTA_F + bsel * CTB_F);
#pragma unroll
        for (int kk = 0; kk < 4; kk++) {
            const int kb = kk * 8;
            unsigned a[2][4];
#pragma unroll
            for (int mt = 0; mt < 2; mt++) {
                const int mb = m0 + mt * 16;
                a[mt][0] = Asu[(mb + lr) * TLD + kb + lc];
                a[mt][1] = Asu[(mb + lr + 8) * TLD + kb + lc];
                a[mt][2] = Asu[(mb + lr) * TLD + kb + lc + 4];
                a[mt][3] = Asu[(mb + lr + 8) * TLD + kb + lc + 4];
            }
#pragma unroll
            for (int nt = 0; nt < 4; nt++) {
                const unsigned b0 = Bsu[(n0 + nt * 8 + lr) * TLD + kb + lc];
                const unsigned b1 = Bsu[(n0 + nt * 8 + lr) * TLD + kb + lc + 4];
                mma_tf32(d[0][nt], a[0][0], a[0][1], a[0][2], a[0][3], b0, b1);
                mma_tf32(d[1][nt], a[1][0], a[1][1], a[1][2], a[1][3], b0, b1);
            }
        }
        __syncthreads();   // all warps done reading buf before it is reissued
    }

    const int er = lane >> 2, ec = 2 * (lane & 3);
#pragma unroll
    for (int mt = 0; mt < 2; mt++)
#pragma unroll
        for (int nt = 0; nt < 4; nt++) {
            const int r = r0 + m0 + mt * 16 + er;
            const int c = c0 + n0 + nt * 8 + ec;
            const int bb = r >> 9, tt = r & 511;
            const float2 v0 = make_float2(d[mt][nt][0], d[mt][nt][1]);
            const float2 v1 = make_float2(d[mt][nt][2], d[mt][nt][3]);
            *(float2*)&tot_out[(size_t)r * OUTD + c]       = v0;
            *(float2*)&tot_out[(size_t)(r + 8) * OUTD + c] = v1;
            *(float2*)&outT[((size_t)tt * BATCH + bb) * OUTD + c]       = v0;
            *(float2*)&outT[((size_t)(tt + 8) * BATCH + bb) * OUTD + c] = v1;
        }
}

// =====================================================================
// launch
// =====================================================================
extern "C" void kernel_launch(void* const* d_in, const int* in_sizes, int n_in,
                              void* d_out, int out_size)
{
    const float* x    = (const float*)d_in[0];
    const float* Win  = (const float*)d_in[1];
    const float* Wr   = (const float*)d_in[2];
    const float* bias = (const float*)d_in[3];
    const float* Wout = (const float*)d_in[4];

    float* out    = (float*)d_out;
    float* o_outT = out + O_OUTT;
    float* o_ip   = out + O_IP;
    float* o_hid  = out + O_HID;
    float* o_out  = out + O_OUT;

    // reset flag counters each launch (graph-capturable, deterministic replays)
    void* p1 = nullptr;
    cudaGetSymbolAddress(&p1, g_tflag);
    cudaMemsetAsync(p1, 0, (size_t)TSQ * 8 * FPAD * sizeof(unsigned));

    const int smemScan = (48 * AUW) * 4 + 1536 * 4;              // 105216 bytes
    cudaFuncSetAttribute(rnn_scan_kernel, cudaFuncAttributeMaxDynamicSharedMemorySize, smemScan);
    const int smemC = (2 * CTA_F + 2 * CTB_F) * (int)sizeof(float);   // 55296 bytes
    cudaFuncSetAttribute(output_kernel, cudaFuncAttributeMaxDynamicSharedMemorySize, smemC);

    // 0) one-shot transpose + tf32 convert of Win / Wout
    transpose_cvt_kernel<<<512, 256>>>(Win, Wout);

    // 1) input projection (tf32 tensor cores)
    input_proj_kernel<<<dim3(HID / 64, (TSQ * BATCH) / 128), 256>>>(x, o_ip);

    // 2) persistent single-hop recurrent scan: 128 CTAs (all resident in wave 1)
    rnn_scan_kernel<<<128, 256, smemScan>>>(o_ip, Wr, bias, o_hid);

    // 3) output projection + transpose (tf32 tensor cores, cp.async pipelined)
    output_kernel<<<dim3(OUTD / 64, (TSQ * BATCH) / 128), 256, smemC>>>(o_out, o_outT);
}